// round 16
// baseline (speedup 1.0000x reference)
#include <cuda_runtime.h>
#include <cuda_fp16.h>
#include <cstdint>
#include <math.h>

#define BB 16
#define CC 512
#define SS 1024
#define PER_B (CC*SS)

typedef __half f16;

// ---------------- scratch (__device__ globals; no allocs) ----------------
__device__ float g_psum[BB*64], g_psq[BB*64], g_stats[BB*2];
__device__ unsigned g_ctr;
__device__ f16  g_h2 [(size_t)BB*SS*512];    // norm'd [B*S, C] fp16 (A-side; also B-side of scores)
__device__ f16  g_w1v[512*512];              // V weights fp16 (B-side)
__device__ f16  g_w2 [512*512];              // proj_w fp16 (A-side for proj)
__device__ f16  g_ut [512*512];              // U^T fp16: g_ut[c'*512+c] = U[c,c']
__device__ float g_v [512];                  // v = bq . Wk  (fp32)
__device__ f16  g_q2 [(size_t)BB*SS*512];    // T = scale*(h U + v) fp16 (A-side of scores)
__device__ f16  g_v2 [(size_t)BB*CC*1024];   // V transposed [B,C,S] fp16 (B-side)
__device__ f16  g_p2 [(size_t)BB*SS*1024];   // probs [B*S, S] fp16 (A-side)
__device__ f16  g_ao2[(size_t)BB*SS*512];    // attn out fp16 (B-side for proj)
__device__ f16  g_scf[(size_t)BB*SS*SS];     // scores fp16

// ---------------- helpers ----------------
__device__ __forceinline__ uint32_t smem_u32(const void* p) {
    uint32_t a;
    asm("{ .reg .u64 t; cvta.to.shared.u64 t, %1; cvt.u32.u64 %0, t; }" : "=r"(a) : "l"(p));
    return a;
}
#define CP_ASYNC16(dst, src) \
    asm volatile("cp.async.cg.shared.global [%0], [%1], 16;" :: "r"(dst), "l"(src) : "memory")
#define CP_COMMIT() asm volatile("cp.async.commit_group;" ::: "memory")
#define CP_WAIT0()  asm volatile("cp.async.wait_group 0;" ::: "memory")
#define CP_WAIT1()  asm volatile("cp.async.wait_group 1;" ::: "memory")
#define CP_WAIT2()  asm volatile("cp.async.wait_group 2;" ::: "memory")
#define LDM_X4(r0,r1,r2,r3,addr) \
    asm volatile("ldmatrix.sync.aligned.m8n8.x4.shared.b16 {%0,%1,%2,%3}, [%4];" \
        : "=r"(r0),"=r"(r1),"=r"(r2),"=r"(r3) : "r"(addr))
#define MMA16816(d, a, b0, b1) \
    asm volatile("mma.sync.aligned.m16n8k16.row.col.f32.f16.f16.f32 " \
        "{%0,%1,%2,%3}, {%4,%5,%6,%7}, {%8,%9}, {%0,%1,%2,%3};" \
        : "+f"((d)[0]), "+f"((d)[1]), "+f"((d)[2]), "+f"((d)[3]) \
        : "r"((a)[0]), "r"((a)[1]), "r"((a)[2]), "r"((a)[3]), "r"(b0), "r"(b1))

// ---------------- fused prologue: GN stats + wconv + v + U ----------------
// blocks [0,1024): GN partial+finalize
// blocks [1024,1536): wconv float4 (V weights + proj weights)
// blocks [1536,1538): v[c'] = sum_o bq[o]*Wk[o,c']
// blocks [1538,1794): U tiles: U[c,c'] = sum_o Wq[o,c]*Wk[o,c'] -> g_ut[c'*512+c]
__global__ void prologue(const float* __restrict__ x,
                         const float* __restrict__ w1s,
                         const float* __restrict__ w2s,
                         const float* __restrict__ qb) {
    int t = threadIdx.x;
    int bid = blockIdx.x;
    if (bid >= 1538) {
        // ---- U tile: 32 (c) x 32 (c') per block, 256 threads ----
        __shared__ float aq[32][33], ak[32][33];
        int ub = bid - 1538;
        int cb = (ub & 15) * 32, cb2 = (ub >> 4) * 32;
        int tx = t & 31, ty8 = t >> 5;
        float acc[4] = {0.f, 0.f, 0.f, 0.f};
        for (int o0 = 0; o0 < 512; o0 += 32) {
#pragma unroll
            for (int i = 0; i < 4; i++) {
                int idx = t + i*256, oo = idx >> 5, cc = idx & 31;
                aq[oo][cc] = w1s[(size_t)(o0 + oo)*512 + cb + cc];
                ak[oo][cc] = w1s[(size_t)(512 + o0 + oo)*512 + cb2 + cc];
            }
            __syncthreads();
#pragma unroll
            for (int oo = 0; oo < 32; oo++) {
                float a = aq[oo][tx];
#pragma unroll
                for (int j = 0; j < 4; j++)
                    acc[j] = fmaf(a, ak[oo][ty8 + 8*j], acc[j]);
            }
            __syncthreads();
        }
#pragma unroll
        for (int j = 0; j < 4; j++)
            g_ut[(size_t)(cb2 + ty8 + 8*j)*512 + cb + tx] = __float2half_rn(acc[j]);
        return;
    }
    if (bid >= 1536) {
        // ---- v[c'] ----
        int c = (bid - 1536) * 256 + t;
        float acc = 0.f;
        for (int o = 0; o < 512; o++)
            acc = fmaf(qb[o], w1s[(size_t)(512 + o)*512 + c], acc);
        g_v[c] = acc;
        return;
    }
    if (bid >= 1024) {
        // ---- weight convert: V weights then proj weights ----
        int i = ((bid - 1024) * 256 + t) * 4;
        float4 v;
        f16* dst;
        if (i < 262144) { v = *(const float4*)&w1s[1024*512 + i]; dst = g_w1v + i; }
        else            { v = *(const float4*)&w2s[i - 262144];   dst = g_w2 + (i - 262144); }
        *(__half2*)&dst[0] = __floats2half2_rn(v.x, v.y);
        *(__half2*)&dst[2] = __floats2half2_rn(v.z, v.w);
        return;
    }
    // ---- GN stats ----
    int b = bid >> 6, chunk = bid & 63;
    const float* p = x + (size_t)b*PER_B + (size_t)chunk*8192;
    float s = 0.f, q = 0.f;
#pragma unroll
    for (int i = 0; i < 32; i++) { float v = p[t + i*256]; s += v; q += v*v; }
    __shared__ float ss_[8], sq_[8];
    for (int o = 16; o > 0; o >>= 1) {
        s += __shfl_down_sync(0xffffffffu, s, o);
        q += __shfl_down_sync(0xffffffffu, q, o);
    }
    if ((t & 31) == 0) { ss_[t >> 5] = s; sq_[t >> 5] = q; }
    __syncthreads();
    __shared__ int isLast;
    if (t == 0) {
        float S2 = 0.f, Q2 = 0.f;
#pragma unroll
        for (int i = 0; i < 8; i++) { S2 += ss_[i]; Q2 += sq_[i]; }
        g_psum[b*64 + chunk] = S2; g_psq[b*64 + chunk] = Q2;
        __threadfence();
        unsigned v = atomicAdd(&g_ctr, 1u);
        isLast = (v == 64u*BB - 1u);
    }
    __syncthreads();
    if (isLast) {
        if (t < BB) {
            float s2 = 0.f, q2 = 0.f;
            for (int i = 0; i < 64; i++) { s2 += g_psum[t*64+i]; q2 += g_psq[t*64+i]; }
            float mean = s2 * (1.f/(float)PER_B);
            float var  = q2 * (1.f/(float)PER_B) - mean*mean;
            g_stats[2*t] = mean; g_stats[2*t+1] = rsqrtf(var + 1e-5f);
        }
        if (t == 0) g_ctr = 0u;
    }
}

// ---------------- normalize + transpose -> g_h2 [B*S, C] fp16 ----------------
__global__ void norm_split(const float* __restrict__ x,
                           const float* __restrict__ gw,
                           const float* __restrict__ gb) {
    __shared__ float tile[32][33];
    int b = blockIdx.z;
    int s0 = blockIdx.x * 32, c0 = blockIdx.y * 32;
    int tx = threadIdx.x, ty = threadIdx.y;
    const float* xp = x + (size_t)b * PER_B;
#pragma unroll
    for (int i = 0; i < 4; i++) {
        int c = c0 + ty + i*8;
        tile[ty + i*8][tx] = xp[(size_t)c*SS + s0 + tx];
    }
    __syncthreads();
    float mean = g_stats[2*b], inv = g_stats[2*b+1];
    int c = c0 + tx;
    float w  = gw[c] * inv;
    float bias = gb[c] - mean * w;
#pragma unroll
    for (int i = 0; i < 4; i++) {
        int s = s0 + ty + i*8;
        float v = tile[tx][ty + i*8] * w + bias;
        g_h2[((size_t)b*SS + s) * 512 + c] = __float2half_rn(v);
    }
}

// ---------------- HMMA GEMM: 128x128 CTA, 8 warps (32x64 each), BK=32, 4-stage ----------------
// NT: out[m,n] = sum_k A[m,k]*B[n,k]
// EPI: 0 = V (staged transpose +bias), 1 = scores fp16, 2 = AV out,
//      3 = proj^T +bias+resid, 4 = T out: (acc+v[n])*scale fp16
#define STAGE_BYTES 20480
#define DYN_SMEM 81920

__device__ __forceinline__ void prefetch_tile(char* smem, int stage,
    const f16* __restrict__ A, int lda, const f16* __restrict__ B, int ldb,
    int m0, int n0, int k0, int tid)
{
    char* as = smem + stage*STAGE_BYTES;
    char* bs = as + 10240;
    int row = tid >> 1, seg = tid & 1;
    const f16* ag = A + (size_t)(m0 + row)*lda + k0 + seg*16;
    const f16* bg = B + (size_t)(n0 + row)*ldb + k0 + seg*16;
    uint32_t asw = smem_u32(as + row*80 + seg*32);
    uint32_t bsw = smem_u32(bs + row*80 + seg*32);
    CP_ASYNC16(asw,      (const void*)ag);
    CP_ASYNC16(asw + 16, (const void*)(ag + 8));
    CP_ASYNC16(bsw,      (const void*)bg);
    CP_ASYNC16(bsw + 16, (const void*)(bg + 8));
}

template<int EPI>
__global__ __launch_bounds__(256, 2)
void mm_gemm(const f16* __restrict__ A, int lda, long long sA,
             const f16* __restrict__ B, int ldb, long long sB,
             float* __restrict__ Out,
             const float* __restrict__ bias,
             const float* __restrict__ resid,
             float scale, int K)
{
    extern __shared__ char smem[];
    int tid = threadIdx.x, lane = tid & 31, wid = tid >> 5;
    int wm = wid >> 1, wn = wid & 1;
    int z = blockIdx.z;
    int m0 = blockIdx.y * 128, n0 = blockIdx.x * 128;
    A += (size_t)z * sA;
    B += (size_t)z * sB;

    float acc[2][8][4];
#pragma unroll
    for (int i = 0; i < 2; i++)
#pragma unroll
        for (int j = 0; j < 8; j++)
#pragma unroll
            for (int r = 0; r < 4; r++) acc[i][j][r] = 0.f;

    uint32_t a_off = (uint32_t)((wm*32 + (lane & 15)) * 80 + (lane >> 4) * 16);
    uint32_t b_off = (uint32_t)((wn*64 + (lane & 7) + ((lane >> 4) << 3)) * 80
                                + ((lane >> 3) & 1) * 16);
    uint32_t smem_base = smem_u32(smem);

    int nch = K >> 5;
#pragma unroll
    for (int p = 0; p < 3; p++) {
        if (p < nch) { prefetch_tile(smem, p, A, lda, B, ldb, m0, n0, p*32, tid); CP_COMMIT(); }
    }

    int st = 0;
    for (int c = 0; c < nch; c++) {
        int rem = nch - 1 - c;
        if (rem >= 2) CP_WAIT2(); else if (rem == 1) CP_WAIT1(); else CP_WAIT0();
        __syncthreads();
        if (c + 3 < nch) {
            prefetch_tile(smem, (st + 3) & 3, A, lda, B, ldb, m0, n0, (c+3)*32, tid);
            CP_COMMIT();
        }

        uint32_t as_b = smem_base + st*STAGE_BYTES + a_off;
        uint32_t bs_b = smem_base + st*STAGE_BYTES + 10240 + b_off;
#pragma unroll
        for (int ks = 0; ks < 2; ks++) {
            uint32_t a[2][4], b[4][4];
#pragma unroll
            for (int mf = 0; mf < 2; mf++)
                LDM_X4(a[mf][0], a[mf][1], a[mf][2], a[mf][3], as_b + mf*1280 + ks*32);
#pragma unroll
            for (int nf2 = 0; nf2 < 4; nf2++)
                LDM_X4(b[nf2][0], b[nf2][1], b[nf2][2], b[nf2][3], bs_b + nf2*1280 + ks*32);
#pragma unroll
            for (int mf = 0; mf < 2; mf++)
#pragma unroll
                for (int nf = 0; nf < 8; nf++)
                    MMA16816(acc[mf][nf], a[mf], b[nf>>1][(nf&1)*2], b[nf>>1][(nf&1)*2+1]);
        }
        st = (st + 1) & 3;
    }

    int r4 = lane >> 2, cp = (lane & 3) * 2;

    if constexpr (EPI == 0) {        // V: staged transpose -> [B,C,S], +bias
        __syncthreads();
        float* tile = (float*)smem;
#pragma unroll
        for (int mf = 0; mf < 2; mf++)
#pragma unroll
            for (int nf = 0; nf < 8; nf++) {
                int rr = wm*32 + mf*16 + r4, cc = wn*64 + nf*8 + cp;
                tile[rr*132 + cc]       = acc[mf][nf][0];
                tile[rr*132 + cc + 1]   = acc[mf][nf][1];
                tile[(rr+8)*132 + cc]   = acc[mf][nf][2];
                tile[(rr+8)*132 + cc+1] = acc[mf][nf][3];
            }
        __syncthreads();
        for (int idx = tid; idx < 16384; idx += 256) {
            int rt = idx & 127, ct = idx >> 7;
            float v = tile[rt*132 + ct] + bias[n0 + ct];
            int m = m0 + rt, b = m >> 10, s = m & 1023;
            int cg = n0 + ct;
            g_v2[((size_t)b*512 + cg) * 1024 + s] = __float2half_rn(v);
        }
    } else if constexpr (EPI == 1) { // scores fp16
        f16* op = g_scf + (size_t)z * SS * SS;
#pragma unroll
        for (int mf = 0; mf < 2; mf++)
#pragma unroll
            for (int nf = 0; nf < 8; nf++) {
                int rr = m0 + wm*32 + mf*16 + r4;
                int cc = n0 + wn*64 + nf*8 + cp;
                *(__half2*)&op[(size_t)rr * SS + cc] =
                    __floats2half2_rn(acc[mf][nf][0], acc[mf][nf][1]);
                *(__half2*)&op[(size_t)(rr + 8) * SS + cc] =
                    __floats2half2_rn(acc[mf][nf][2], acc[mf][nf][3]);
            }
    } else if constexpr (EPI == 2) { // AV direct half2
#pragma unroll
        for (int mf = 0; mf < 2; mf++)
#pragma unroll
            for (int nf = 0; nf < 8; nf++) {
                int rr = m0 + wm*32 + mf*16 + r4;
                int cc = n0 + wn*64 + nf*8 + cp;
                *(__half2*)&g_ao2[((size_t)z * SS + rr) * 512 + cc] =
                    __floats2half2_rn(acc[mf][nf][0], acc[mf][nf][1]);
                *(__half2*)&g_ao2[((size_t)z * SS + rr + 8) * 512 + cc] =
                    __floats2half2_rn(acc[mf][nf][2], acc[mf][nf][3]);
            }
    } else if constexpr (EPI == 4) { // T = (acc + v[n]) * scale -> g_q2 fp16
#pragma unroll
        for (int mf = 0; mf < 2; mf++)
#pragma unroll
            for (int nf = 0; nf < 8; nf++) {
                int rr = m0 + wm*32 + mf*16 + r4;
                int cc = wn*64 + nf*8 + cp;
                float v0 = g_v[n0 + cc], v1 = g_v[n0 + cc + 1];
                *(__half2*)&g_q2[(size_t)rr * 512 + n0 + cc] =
                    __floats2half2_rn((acc[mf][nf][0] + v0)*scale, (acc[mf][nf][1] + v1)*scale);
                *(__half2*)&g_q2[(size_t)(rr + 8) * 512 + n0 + cc] =
                    __floats2half2_rn((acc[mf][nf][2] + v0)*scale, (acc[mf][nf][3] + v1)*scale);
            }
    } else {                         // proj^T: m=c-dim, n=global s; +bias+resid
#pragma unroll
        for (int mf = 0; mf < 2; mf++) {
            int rr = m0 + wm*32 + mf*16 + r4;
            float bias_r  = bias[rr], bias_r8 = bias[rr + 8];
#pragma unroll
            for (int nf = 0; nf < 8; nf++) {
                int n = n0 + wn*64 + nf*8 + cp;
                int b = n >> 10, s = n & 1023;
                size_t o0 = ((size_t)b * 512 + rr) * 1024 + s;
                size_t o1 = ((size_t)b * 512 + rr + 8) * 1024 + s;
                float2 rv0 = *(const float2*)&resid[o0];
                float2 rv1 = *(const float2*)&resid[o1];
                float2 w0 = {acc[mf][nf][0] + bias_r  + rv0.x, acc[mf][nf][1] + bias_r  + rv0.y};
                float2 w1 = {acc[mf][nf][2] + bias_r8 + rv1.x, acc[mf][nf][3] + bias_r8 + rv1.y};
                *(float2*)&Out[o0] = w0;
                *(float2*)&Out[o1] = w1;
            }
        }
    }
}

// ---------------- softmax over 1024-wide fp16 rows, fp16 output ----------------
__global__ void softmax_rows() {
    const f16* row = g_scf + (size_t)blockIdx.x * SS;
    f16* orow = g_p2 + (size_t)blockIdx.x * 1024;
    int t = threadIdx.x;
    float v[4];
    {
        __half2 h0 = *(const __half2*)&row[t*2];
        __half2 h1 = *(const __half2*)&row[512 + t*2];
        float2 f0 = __half22float2(h0), f1 = __half22float2(h1);
        v[0] = f0.x; v[1] = f0.y; v[2] = f1.x; v[3] = f1.y;
    }
    float m = fmaxf(fmaxf(v[0], v[1]), fmaxf(v[2], v[3]));
    __shared__ float red[8];
    for (int o = 16; o > 0; o >>= 1) m = fmaxf(m, __shfl_xor_sync(0xffffffffu, m, o));
    if ((t & 31) == 0) red[t >> 5] = m;
    __syncthreads();
    float mm = fmaxf(fmaxf(fmaxf(red[0], red[1]), fmaxf(red[2], red[3])),
                     fmaxf(fmaxf(red[4], red[5]), fmaxf(red[6], red[7])));
    float s = 0.f;
#pragma unroll
    for (int i = 0; i < 4; i++) { v[i] = __expf(v[i] - mm); s += v[i]; }
    for (int o = 16; o > 0; o >>= 1) s += __shfl_xor_sync(0xffffffffu, s, o);
    __syncthreads();
    if ((t & 31) == 0) red[t >> 5] = s;
    __syncthreads();
    float tot = ((red[0]+red[1]) + (red[2]+red[3])) + ((red[4]+red[5]) + (red[6]+red[7]));
    float invs = 1.f / tot;
    *(__half2*)&orow[t*2]       = __floats2half2_rn(v[0] * invs, v[1] * invs);
    *(__half2*)&orow[512 + t*2] = __floats2half2_rn(v[2] * invs, v[3] * invs);
}

// ---------------- launch ----------------
extern "C" void kernel_launch(void* const* d_in, const int* in_sizes, int n_in,
                              void* d_out, int out_size) {
    const float* x      = (const float*)d_in[0];
    const float* gn_w   = (const float*)d_in[1];
    const float* gn_b   = (const float*)d_in[2];
    const float* qkv_w  = (const float*)d_in[3];
    const float* qkv_b  = (const float*)d_in[4];
    const float* proj_w = (const float*)d_in[5];
    const float* proj_b = (const float*)d_in[6];
    float* out = (float*)d_out;

    cudaFuncSetAttribute(mm_gemm<0>, cudaFuncAttributeMaxDynamicSharedMemorySize, DYN_SMEM);
    cudaFuncSetAttribute(mm_gemm<1>, cudaFuncAttributeMaxDynamicSharedMemorySize, DYN_SMEM);
    cudaFuncSetAttribute(mm_gemm<2>, cudaFuncAttributeMaxDynamicSharedMemorySize, DYN_SMEM);
    cudaFuncSetAttribute(mm_gemm<3>, cudaFuncAttributeMaxDynamicSharedMemorySize, DYN_SMEM);
    cudaFuncSetAttribute(mm_gemm<4>, cudaFuncAttributeMaxDynamicSharedMemorySize, DYN_SMEM);

    f16 *h2, *w1v, *w2, *ut, *q2, *v2, *p2, *ao2;
    cudaGetSymbolAddress((void**)&h2,  g_h2);
    cudaGetSymbolAddress((void**)&w1v, g_w1v);
    cudaGetSymbolAddress((void**)&w2,  g_w2);
    cudaGetSymbolAddress((void**)&ut,  g_ut);
    cudaGetSymbolAddress((void**)&q2,  g_q2);
    cudaGetSymbolAddress((void**)&v2,  g_v2);
    cudaGetSymbolAddress((void**)&p2,  g_p2);
    cudaGetSymbolAddress((void**)&ao2, g_ao2);

    // 1. fused prologue: GN stats + wconv + v + U
    prologue<<<1794, 256>>>(x, qkv_w, proj_w, qkv_b);

    // 2. normalize + transpose (fp16)
    norm_split<<<dim3(SS/32, CC/32, BB), dim3(32, 8)>>>(x, gn_w, gn_b);

    // 3. V GEMM: M=16384, N=512, K=512 (staged transpose to [B,C,S])
    mm_gemm<0><<<dim3(4, 128, 1), 256, DYN_SMEM>>>(
        h2, 512, 0LL, w1v, 512, 0LL,
        nullptr, qkv_b + 1024, nullptr, 1.f, 512);

    // 4. T GEMM: T = scale*(h U + v): M=16384, N=512, K=512
    mm_gemm<4><<<dim3(4, 128, 1), 256, DYN_SMEM>>>(
        h2, 512, 0LL, ut, 512, 0LL,
        nullptr, nullptr, nullptr, 0.044194173824159216f, 512);

    // 5. scores = T h^T -> fp16, batched: K=512
    mm_gemm<1><<<dim3(8, 8, BB), 256, DYN_SMEM>>>(
        q2, 512, 1024LL*512, h2, 512, 1024LL*512, nullptr,
        nullptr, nullptr, 1.f, 512);

    // 6. softmax (fp16 in/out)
    softmax_rows<<<BB*SS, 256>>>();

    // 7. attn @ V: M=1024, N=512, K=1024, batched
    mm_gemm<2><<<dim3(4, 8, BB), 256, DYN_SMEM>>>(
        p2, 1024, 1024LL*1024, v2, 1024, 512LL*1024, nullptr,
        nullptr, nullptr, 1.f, 1024);

    // 8. proj^T + bias + residual -> NCHW out: M=512 (c), N=16384 (b*s), K=512
    mm_gemm<3><<<dim3(128, 4, 1), 256, DYN_SMEM>>>(
        w2, 512, 0LL, ao2, 512, 0LL, out, proj_b, x, 1.f, 512);
}

// round 17
// speedup vs baseline: 1.1090x; 1.1090x over previous
#include <cuda_runtime.h>
#include <cuda_fp16.h>
#include <cstdint>
#include <math.h>

#define BB 16
#define CC 512
#define SS 1024
#define PER_B (CC*SS)

typedef __half f16;

// ---------------- scratch (__device__ globals; no allocs) ----------------
__device__ float g_psum[BB*64], g_psq[BB*64], g_stats[BB*2];
__device__ unsigned g_ctr;
__device__ f16  g_h2 [(size_t)BB*SS*512];    // norm'd [B*S, C] fp16 (A-side; B-side of scores)
__device__ f16  g_wqT[512*512];              // Wq^T fp16 [c, o]
__device__ f16  g_wkT[512*512];              // Wk^T fp16 [c, o]
__device__ f16  g_btv[1024*512];             // rows 0-511: Ut (B of T); rows 512-1023: Wv (B of V)
__device__ f16  g_w2 [512*512];              // proj_w fp16 (A-side for proj)
__device__ float g_v [512];                  // v = bq . Wk (fp32)
__device__ f16  g_q2 [(size_t)BB*SS*512];    // T = scale*(h U + v) fp16 (A-side of scores)
__device__ f16  g_v2 [(size_t)BB*CC*1024];   // V transposed [B,C,S] fp16 (B-side)
__device__ f16  g_p2 [(size_t)BB*SS*1024];   // e = exp(scores) fp16 (A-side of AV)
__device__ float g_l [(size_t)BB*SS];        // row sums of e (fp32)
__device__ f16  g_ao2[(size_t)BB*SS*512];    // attn out fp16 (B-side for proj)

// ---------------- helpers ----------------
__device__ __forceinline__ uint32_t smem_u32(const void* p) {
    uint32_t a;
    asm("{ .reg .u64 t; cvta.to.shared.u64 t, %1; cvt.u32.u64 %0, t; }" : "=r"(a) : "l"(p));
    return a;
}
#define CP_ASYNC16(dst, src) \
    asm volatile("cp.async.cg.shared.global [%0], [%1], 16;" :: "r"(dst), "l"(src) : "memory")
#define CP_COMMIT() asm volatile("cp.async.commit_group;" ::: "memory")
#define CP_WAIT0()  asm volatile("cp.async.wait_group 0;" ::: "memory")
#define CP_WAIT1()  asm volatile("cp.async.wait_group 1;" ::: "memory")
#define CP_WAIT2()  asm volatile("cp.async.wait_group 2;" ::: "memory")
#define LDM_X4(r0,r1,r2,r3,addr) \
    asm volatile("ldmatrix.sync.aligned.m8n8.x4.shared.b16 {%0,%1,%2,%3}, [%4];" \
        : "=r"(r0),"=r"(r1),"=r"(r2),"=r"(r3) : "r"(addr))
#define MMA16816(d, a, b0, b1) \
    asm volatile("mma.sync.aligned.m16n8k16.row.col.f32.f16.f16.f32 " \
        "{%0,%1,%2,%3}, {%4,%5,%6,%7}, {%8,%9}, {%0,%1,%2,%3};" \
        : "+f"((d)[0]), "+f"((d)[1]), "+f"((d)[2]), "+f"((d)[3]) \
        : "r"((a)[0]), "r"((a)[1]), "r"((a)[2]), "r"((a)[3]), "r"(b0), "r"(b1))

// ---------------- fused prologue ----------------
// [0,1024): GN stats; [1024,1536): wconv (Wv -> g_btv+512rows, proj -> g_w2)
// [1536,2048): Wq/Wk fp16 transposes; [2048,2050): v = bq.Wk
__global__ void prologue(const float* __restrict__ x,
                         const float* __restrict__ w1s,
                         const float* __restrict__ w2s,
                         const float* __restrict__ qb) {
    int t = threadIdx.x;
    int bid = blockIdx.x;
    if (bid >= 2048) {
        int c = (bid - 2048) * 256 + t;
        float acc = 0.f;
        for (int o = 0; o < 512; o++)
            acc = fmaf(qb[o], w1s[(size_t)(512 + o)*512 + c], acc);
        g_v[c] = acc;
        return;
    }
    if (bid >= 1536) {
        __shared__ float tile[32][33];
        int tt = bid - 1536;
        int mtx = tt >> 8;            // 0 = Wq, 1 = Wk
        int tile_i = tt & 255;
        int ob = (tile_i & 15) * 32;
        int cb = (tile_i >> 4) * 32;
        int tx = t & 31, ty = t >> 5;
        const float* W = w1s + (size_t)mtx * 512 * 512;
#pragma unroll
        for (int k = 0; k < 4; k++)
            tile[ty + 8*k][tx] = W[(size_t)(ob + ty + 8*k) * 512 + cb + tx];
        __syncthreads();
        f16* dst = mtx ? g_wkT : g_wqT;
#pragma unroll
        for (int k = 0; k < 4; k++)
            dst[(size_t)(cb + ty + 8*k) * 512 + ob + tx] = __float2half_rn(tile[tx][ty + 8*k]);
        return;
    }
    if (bid >= 1024) {
        int i = ((bid - 1024) * 256 + t) * 4;
        float4 v;
        f16* dst;
        if (i < 262144) { v = *(const float4*)&w1s[524288 + i]; dst = g_btv + 262144 + i; }
        else            { v = *(const float4*)&w2s[i - 262144]; dst = g_w2 + (i - 262144); }
        *(__half2*)&dst[0] = __floats2half2_rn(v.x, v.y);
        *(__half2*)&dst[2] = __floats2half2_rn(v.z, v.w);
        return;
    }
    // GN stats
    int b = bid >> 6, chunk = bid & 63;
    const float* p = x + (size_t)b*PER_B + (size_t)chunk*8192;
    float s = 0.f, q = 0.f;
#pragma unroll
    for (int i = 0; i < 32; i++) { float v = p[t + i*256]; s += v; q += v*v; }
    __shared__ float ss_[8], sq_[8];
    for (int o = 16; o > 0; o >>= 1) {
        s += __shfl_down_sync(0xffffffffu, s, o);
        q += __shfl_down_sync(0xffffffffu, q, o);
    }
    if ((t & 31) == 0) { ss_[t >> 5] = s; sq_[t >> 5] = q; }
    __syncthreads();
    __shared__ int isLast;
    if (t == 0) {
        float S2 = 0.f, Q2 = 0.f;
#pragma unroll
        for (int i = 0; i < 8; i++) { S2 += ss_[i]; Q2 += sq_[i]; }
        g_psum[b*64 + chunk] = S2; g_psq[b*64 + chunk] = Q2;
        __threadfence();
        unsigned v = atomicAdd(&g_ctr, 1u);
        isLast = (v == 64u*BB - 1u);
    }
    __syncthreads();
    if (isLast) {
        if (t < BB) {
            float s2 = 0.f, q2 = 0.f;
            for (int i = 0; i < 64; i++) { s2 += g_psum[t*64+i]; q2 += g_psq[t*64+i]; }
            float mean = s2 * (1.f/(float)PER_B);
            float var  = q2 * (1.f/(float)PER_B) - mean*mean;
            g_stats[2*t] = mean; g_stats[2*t+1] = rsqrtf(var + 1e-5f);
        }
        if (t == 0) g_ctr = 0u;
    }
}

// ---------------- normalize + transpose -> g_h2 [B*S, C] fp16 ----------------
__global__ void norm_split(const float* __restrict__ x,
                           const float* __restrict__ gw,
                           const float* __restrict__ gb) {
    __shared__ float tile[32][33];
    int b = blockIdx.z;
    int s0 = blockIdx.x * 32, c0 = blockIdx.y * 32;
    int tx = threadIdx.x, ty = threadIdx.y;
    const float* xp = x + (size_t)b * PER_B;
#pragma unroll
    for (int i = 0; i < 4; i++) {
        int c = c0 + ty + i*8;
        tile[ty + i*8][tx] = xp[(size_t)c*SS + s0 + tx];
    }
    __syncthreads();
    float mean = g_stats[2*b], inv = g_stats[2*b+1];
    int c = c0 + tx;
    float w  = gw[c] * inv;
    float bias = gb[c] - mean * w;
#pragma unroll
    for (int i = 0; i < 4; i++) {
        int s = s0 + ty + i*8;
        float v = tile[tx][ty + i*8] * w + bias;
        g_h2[((size_t)b*SS + s) * 512 + c] = __float2half_rn(v);
    }
}

// ---------------- HMMA GEMM: 128x128 CTA, 8 warps (32x64 each), BK=32, 4-stage ----------------
// NT: out[m,n] = sum_k A[m,k]*B[n,k]
// EPI: 0 = TV (T: (acc+v[n])*scale; V: staged transpose +bias), 1 = scores -> exp fp16,
//      2 = AV / l, 3 = proj^T +bias+resid, 5 = U store fp16 -> g_btv
#define STAGE_BYTES 20480
#define DYN_SMEM 81920

__device__ __forceinline__ void prefetch_tile(char* smem, int stage,
    const f16* __restrict__ A, int lda, const f16* __restrict__ B, int ldb,
    int m0, int n0, int k0, int tid)
{
    char* as = smem + stage*STAGE_BYTES;
    char* bs = as + 10240;
    int row = tid >> 1, seg = tid & 1;
    const f16* ag = A + (size_t)(m0 + row)*lda + k0 + seg*16;
    const f16* bg = B + (size_t)(n0 + row)*ldb + k0 + seg*16;
    uint32_t asw = smem_u32(as + row*80 + seg*32);
    uint32_t bsw = smem_u32(bs + row*80 + seg*32);
    CP_ASYNC16(asw,      (const void*)ag);
    CP_ASYNC16(asw + 16, (const void*)(ag + 8));
    CP_ASYNC16(bsw,      (const void*)bg);
    CP_ASYNC16(bsw + 16, (const void*)(bg + 8));
}

template<int EPI>
__global__ __launch_bounds__(256, 2)
void mm_gemm(const f16* __restrict__ A, int lda, long long sA,
             const f16* __restrict__ B, int ldb, long long sB,
             float* __restrict__ Out,
             const float* __restrict__ bias,
             const float* __restrict__ resid,
             float scale, int K)
{
    extern __shared__ char smem[];
    int tid = threadIdx.x, lane = tid & 31, wid = tid >> 5;
    int wm = wid >> 1, wn = wid & 1;
    int z = blockIdx.z;
    int m0 = blockIdx.y * 128, n0 = blockIdx.x * 128;
    A += (size_t)z * sA;
    B += (size_t)z * sB;

    float acc[2][8][4];
#pragma unroll
    for (int i = 0; i < 2; i++)
#pragma unroll
        for (int j = 0; j < 8; j++)
#pragma unroll
            for (int r = 0; r < 4; r++) acc[i][j][r] = 0.f;

    uint32_t a_off = (uint32_t)((wm*32 + (lane & 15)) * 80 + (lane >> 4) * 16);
    uint32_t b_off = (uint32_t)((wn*64 + (lane & 7) + ((lane >> 4) << 3)) * 80
                                + ((lane >> 3) & 1) * 16);
    uint32_t smem_base = smem_u32(smem);

    int nch = K >> 5;
#pragma unroll
    for (int p = 0; p < 3; p++) {
        if (p < nch) { prefetch_tile(smem, p, A, lda, B, ldb, m0, n0, p*32, tid); CP_COMMIT(); }
    }

    int st = 0;
    for (int c = 0; c < nch; c++) {
        int rem = nch - 1 - c;
        if (rem >= 2) CP_WAIT2(); else if (rem == 1) CP_WAIT1(); else CP_WAIT0();
        __syncthreads();
        if (c + 3 < nch) {
            prefetch_tile(smem, (st + 3) & 3, A, lda, B, ldb, m0, n0, (c+3)*32, tid);
            CP_COMMIT();
        }

        uint32_t as_b = smem_base + st*STAGE_BYTES + a_off;
        uint32_t bs_b = smem_base + st*STAGE_BYTES + 10240 + b_off;
#pragma unroll
        for (int ks = 0; ks < 2; ks++) {
            uint32_t a[2][4], b[4][4];
#pragma unroll
            for (int mf = 0; mf < 2; mf++)
                LDM_X4(a[mf][0], a[mf][1], a[mf][2], a[mf][3], as_b + mf*1280 + ks*32);
#pragma unroll
            for (int nf2 = 0; nf2 < 4; nf2++)
                LDM_X4(b[nf2][0], b[nf2][1], b[nf2][2], b[nf2][3], bs_b + nf2*1280 + ks*32);
#pragma unroll
            for (int mf = 0; mf < 2; mf++)
#pragma unroll
                for (int nf = 0; nf < 8; nf++)
                    MMA16816(acc[mf][nf], a[mf], b[nf>>1][(nf&1)*2], b[nf>>1][(nf&1)*2+1]);
        }
        st = (st + 1) & 3;
    }

    int r4 = lane >> 2, cp = (lane & 3) * 2;

    if constexpr (EPI == 0) {        // TV GEMM
        if (n0 < 512) {              // T = (acc + v[n]) * scale -> g_q2
#pragma unroll
            for (int mf = 0; mf < 2; mf++)
#pragma unroll
                for (int nf = 0; nf < 8; nf++) {
                    int rr = m0 + wm*32 + mf*16 + r4;
                    int cc = wn*64 + nf*8 + cp;
                    float v0 = g_v[n0 + cc], v1 = g_v[n0 + cc + 1];
                    *(__half2*)&g_q2[(size_t)rr * 512 + n0 + cc] =
                        __floats2half2_rn((acc[mf][nf][0] + v0)*scale, (acc[mf][nf][1] + v1)*scale);
                    *(__half2*)&g_q2[(size_t)(rr + 8) * 512 + n0 + cc] =
                        __floats2half2_rn((acc[mf][nf][2] + v0)*scale, (acc[mf][nf][3] + v1)*scale);
                }
        } else {                     // V: staged transpose -> [B,C,S], +bias
            __syncthreads();
            float* tile = (float*)smem;
#pragma unroll
            for (int mf = 0; mf < 2; mf++)
#pragma unroll
                for (int nf = 0; nf < 8; nf++) {
                    int rr = wm*32 + mf*16 + r4, cc = wn*64 + nf*8 + cp;
                    tile[rr*132 + cc]       = acc[mf][nf][0];
                    tile[rr*132 + cc + 1]   = acc[mf][nf][1];
                    tile[(rr+8)*132 + cc]   = acc[mf][nf][2];
                    tile[(rr+8)*132 + cc+1] = acc[mf][nf][3];
                }
            __syncthreads();
            for (int idx = tid; idx < 16384; idx += 256) {
                int rt = idx & 127, ct = idx >> 7;
                int cg = n0 + ct - 512;
                float v = tile[rt*132 + ct] + bias[cg];
                int m = m0 + rt, b = m >> 10, s = m & 1023;
                g_v2[((size_t)b*512 + cg) * 1024 + s] = __float2half_rn(v);
            }
        }
    } else if constexpr (EPI == 1) { // scores -> e = exp(s) fp16
        f16* op = g_p2 + (size_t)z * SS * 1024;
#pragma unroll
        for (int mf = 0; mf < 2; mf++)
#pragma unroll
            for (int nf = 0; nf < 8; nf++) {
                int rr = m0 + wm*32 + mf*16 + r4;
                int cc = n0 + wn*64 + nf*8 + cp;
                *(__half2*)&op[(size_t)rr * 1024 + cc] =
                    __floats2half2_rn(__expf(acc[mf][nf][0]), __expf(acc[mf][nf][1]));
                *(__half2*)&op[(size_t)(rr + 8) * 1024 + cc] =
                    __floats2half2_rn(__expf(acc[mf][nf][2]), __expf(acc[mf][nf][3]));
            }
    } else if constexpr (EPI == 2) { // AV / l
#pragma unroll
        for (int mf = 0; mf < 2; mf++) {
            int rr = m0 + wm*32 + mf*16 + r4;
            float il0 = 1.f / g_l[(size_t)z*1024 + rr];
            float il1 = 1.f / g_l[(size_t)z*1024 + rr + 8];
#pragma unroll
            for (int nf = 0; nf < 8; nf++) {
                int cc = n0 + wn*64 + nf*8 + cp;
                *(__half2*)&g_ao2[((size_t)z * SS + rr) * 512 + cc] =
                    __floats2half2_rn(acc[mf][nf][0] * il0, acc[mf][nf][1] * il0);
                *(__half2*)&g_ao2[((size_t)z * SS + rr + 8) * 512 + cc] =
                    __floats2half2_rn(acc[mf][nf][2] * il1, acc[mf][nf][3] * il1);
            }
        }
    } else if constexpr (EPI == 5) { // U -> g_btv rows 0-511
#pragma unroll
        for (int mf = 0; mf < 2; mf++)
#pragma unroll
            for (int nf = 0; nf < 8; nf++) {
                int rr = m0 + wm*32 + mf*16 + r4;
                int cc = n0 + wn*64 + nf*8 + cp;
                *(__half2*)&g_btv[(size_t)rr * 512 + cc] =
                    __floats2half2_rn(acc[mf][nf][0], acc[mf][nf][1]);
                *(__half2*)&g_btv[(size_t)(rr + 8) * 512 + cc] =
                    __floats2half2_rn(acc[mf][nf][2], acc[mf][nf][3]);
            }
    } else {                         // proj^T: m=c-dim, n=global s; +bias+resid
#pragma unroll
        for (int mf = 0; mf < 2; mf++) {
            int rr = m0 + wm*32 + mf*16 + r4;
            float bias_r  = bias[rr], bias_r8 = bias[rr + 8];
#pragma unroll
            for (int nf = 0; nf < 8; nf++) {
                int n = n0 + wn*64 + nf*8 + cp;
                int b = n >> 10, s = n & 1023;
                size_t o0 = ((size_t)b * 512 + rr) * 1024 + s;
                size_t o1 = ((size_t)b * 512 + rr + 8) * 1024 + s;
                float2 rv0 = *(const float2*)&resid[o0];
                float2 rv1 = *(const float2*)&resid[o1];
                float2 w0 = {acc[mf][nf][0] + bias_r  + rv0.x, acc[mf][nf][1] + bias_r  + rv0.y};
                float2 w1 = {acc[mf][nf][2] + bias_r8 + rv1.x, acc[mf][nf][3] + bias_r8 + rv1.y};
                *(float2*)&Out[o0] = w0;
                *(float2*)&Out[o1] = w1;
            }
        }
    }
}

// ---------------- row sums of e: g_l[row] = sum_j e[row, j] ----------------
__global__ void rowsum() {
    const f16* row = g_p2 + (size_t)blockIdx.x * 1024;
    int t = threadIdx.x;
    float2 a = __half22float2(*(const __half2*)&row[t*4]);
    float2 b = __half22float2(*(const __half2*)&row[t*4 + 2]);
    float s = (a.x + a.y) + (b.x + b.y);
    __shared__ float red[8];
    for (int o = 16; o > 0; o >>= 1) s += __shfl_xor_sync(0xffffffffu, s, o);
    if ((t & 31) == 0) red[t >> 5] = s;
    __syncthreads();
    if (t == 0) {
        float tot = ((red[0]+red[1]) + (red[2]+red[3])) + ((red[4]+red[5]) + (red[6]+red[7]));
        g_l[blockIdx.x] = tot;
    }
}

// ---------------- launch ----------------
extern "C" void kernel_launch(void* const* d_in, const int* in_sizes, int n_in,
                              void* d_out, int out_size) {
    const float* x      = (const float*)d_in[0];
    const float* gn_w   = (const float*)d_in[1];
    const float* gn_b   = (const float*)d_in[2];
    const float* qkv_w  = (const float*)d_in[3];
    const float* qkv_b  = (const float*)d_in[4];
    const float* proj_w = (const float*)d_in[5];
    const float* proj_b = (const float*)d_in[6];
    float* out = (float*)d_out;

    cudaFuncSetAttribute(mm_gemm<0>, cudaFuncAttributeMaxDynamicSharedMemorySize, DYN_SMEM);
    cudaFuncSetAttribute(mm_gemm<1>, cudaFuncAttributeMaxDynamicSharedMemorySize, DYN_SMEM);
    cudaFuncSetAttribute(mm_gemm<2>, cudaFuncAttributeMaxDynamicSharedMemorySize, DYN_SMEM);
    cudaFuncSetAttribute(mm_gemm<3>, cudaFuncAttributeMaxDynamicSharedMemorySize, DYN_SMEM);
    cudaFuncSetAttribute(mm_gemm<5>, cudaFuncAttributeMaxDynamicSharedMemorySize, DYN_SMEM);

    f16 *h2, *wqT, *wkT, *btv, *w2, *q2, *v2, *p2, *ao2;
    cudaGetSymbolAddress((void**)&h2,  g_h2);
    cudaGetSymbolAddress((void**)&wqT, g_wqT);
    cudaGetSymbolAddress((void**)&wkT, g_wkT);
    cudaGetSymbolAddress((void**)&btv, g_btv);
    cudaGetSymbolAddress((void**)&w2,  g_w2);
    cudaGetSymbolAddress((void**)&q2,  g_q2);
    cudaGetSymbolAddress((void**)&v2,  g_v2);
    cudaGetSymbolAddress((void**)&p2,  g_p2);
    cudaGetSymbolAddress((void**)&ao2, g_ao2);

    // 1. fused prologue: GN stats + wconv + Wq/Wk transposes + v
    prologue<<<2050, 256>>>(x, qkv_w, proj_w, qkv_b);

    // 2. normalize + transpose (fp16)
    norm_split<<<dim3(SS/32, CC/32, BB), dim3(32, 8)>>>(x, gn_w, gn_b);

    // 3. U GEMM: out[c',c] = sum_o Wk[o,c']*Wq[o,c] = U[c,c'] -> g_btv rows 0-511
    mm_gemm<5><<<dim3(4, 4, 1), 256, DYN_SMEM>>>(
        wkT, 512, 0LL, wqT, 512, 0LL, nullptr, nullptr, nullptr, 1.f, 512);

    // 4. TV GEMM: M=16384, N=1024 ([T | V]), K=512   <-- profiled slot
    mm_gemm<0><<<dim3(8, 128, 1), 256, DYN_SMEM>>>(
        h2, 512, 0LL, btv, 512, 0LL,
        nullptr, qkv_b + 1024, nullptr, 0.044194173824159216f, 512);

    // 5. scores = T h^T -> e = exp fp16, batched: K=512
    mm_gemm<1><<<dim3(8, 8, BB), 256, DYN_SMEM>>>(
        q2, 512, 1024LL*512, h2, 512, 1024LL*512, nullptr,
        nullptr, nullptr, 1.f, 512);

    // 6. row sums
    rowsum<<<BB*SS, 256>>>();

    // 7. attn @ V (/l): M=1024, N=512, K=1024, batched
    mm_gemm<2><<<dim3(4, 8, BB), 256, DYN_SMEM>>>(
        p2, 1024, 1024LL*1024, v2, 1024, 512LL*1024, nullptr,
        nullptr, nullptr, 1.f, 1024);

    // 8. proj^T + bias + residual -> NCHW out
    mm_gemm<3><<<dim3(128, 4, 1), 256, DYN_SMEM>>>(
        w2, 512, 0LL, ao2, 512, 0LL, out, proj_b, x, 1.f, 512);
}